// round 1
// baseline (speedup 1.0000x reference)
#include <cuda_runtime.h>
#include <cuda_bf16.h>
#include <math.h>

// ---------------------------------------------------------------------------
// Problem constants
// ---------------------------------------------------------------------------
#define BATCH 32
#define CIN   256
#define COUT  256
#define HW_H  56
#define HW_W  56
#define HW    (HW_H * HW_W)          // 3136 positions per image
#define KTAPS 9

// Conv tiling
#define OC_TILE   64                 // out channels per block
#define POS_TILE  256                // flattened positions per block
#define CI_CHUNK  8                  // input channels per smem stage
#define THREADS   256

// Scratch ( __device__ globals are the allowed scratch mechanism )
__device__ float g_xb[BATCH * CIN * HW];           // binarized activations, NCHW
__device__ float g_wt[CIN * KTAPS * COUT];         // weights transposed to [ci*9+tap][oc]

// ---------------------------------------------------------------------------
// Kernel 1: binarize  (pair mean of |x| along W, carrying sign of x)
// W=56 is even and rows start at even element offsets -> float2 safe.
// ---------------------------------------------------------------------------
__global__ void binarize_kernel(const float* __restrict__ x, int n2) {
    int i = blockIdx.x * blockDim.x + threadIdx.x;
    if (i >= n2) return;
    float2 v = reinterpret_cast<const float2*>(x)[i];
    float m = 0.5f * (fabsf(v.x) + fabsf(v.y));
    float2 o;
    o.x = (v.x == 0.0f) ? 0.0f : copysignf(m, v.x);
    o.y = (v.y == 0.0f) ? 0.0f : copysignf(m, v.y);
    reinterpret_cast<float2*>(g_xb)[i] = o;
}

// ---------------------------------------------------------------------------
// Kernel 2: weight transpose OIHW -> [ci*9+tap][oc]  (coalesced conv loads)
// ---------------------------------------------------------------------------
__global__ void wtrans_kernel(const float* __restrict__ w) {
    int idx = blockIdx.x * blockDim.x + threadIdx.x;   // over COUT*CIN*9
    if (idx >= COUT * CIN * KTAPS) return;
    int oc  = idx / (CIN * KTAPS);
    int rem = idx % (CIN * KTAPS);                     // ci*9 + tap
    g_wt[rem * COUT + oc] = w[idx];
}

// ---------------------------------------------------------------------------
// Kernel 3: direct 3x3 conv, register-tiled.
//
// Block: 64 oc x 256 flattened positions of one image.
// Thread layout: warp = oc-group (8 warps x 8 oc = 64), lane = pos-group
//                (32 lanes x 8 positions = 256).  Thread's positions are
//                p0 + lane + 32*i  -> lanes consecutive => conflict-free LDS
//                and coalesced STG.  Thread's 8 oc are contiguous => weight
//                fragment is two broadcast LDS.128 per (ci,tap).
// Inner step (ci,tap): 2 LDS.128 + 8 LDS.32 + 64 FFMA  => FFMA-pipe bound.
// ---------------------------------------------------------------------------
__global__ __launch_bounds__(THREADS, 1)
void conv3x3_kernel(const float* __restrict__ bias, float* __restrict__ out) {
    // [ci][row 0..7][col 0..59]  (8 rows = 6 pos rows + 2 halo; 58 used cols)
    __shared__ __align__(16) float s_in[CI_CHUNK * 8 * 60];
    // [ci][tap][oc 0..63]
    __shared__ __align__(16) float s_w[CI_CHUNK * KTAPS * OC_TILE];

    const int tid   = threadIdx.x;
    const int warp  = tid >> 5;      // oc group
    const int lane  = tid & 31;      // pos group

    const int n      = blockIdx.z;
    const int p0     = blockIdx.y * POS_TILE;
    const int h_base = p0 / HW_W;
    const int oc0    = blockIdx.x * OC_TILE + warp * 8;

    // Per-thread position table
    int   pidx[8];
    int   boff[8];
    #pragma unroll
    for (int i = 0; i < 8; i++) {
        int p   = p0 + lane + 32 * i;
        pidx[i] = p;
        int r   = p / HW_W - h_base + 1;   // 1..6 (halo rows at 0 and 7)
        int c   = p % HW_W + 1;            // 1..56
        boff[i] = r * 60 + c;
    }

    float acc[8][8];
    #pragma unroll
    for (int i = 0; i < 8; i++)
        #pragma unroll
        for (int j = 0; j < 8; j++)
            acc[i][j] = 0.0f;

    const float* xb = g_xb + (size_t)n * CIN * HW;

    for (int ci0 = 0; ci0 < CIN; ci0 += CI_CHUNK) {
        __syncthreads();

        // ---- stage input tile: 8 ci x 8 rows x 60 cols (zero-padded) ----
        #pragma unroll
        for (int k = 0; k < (CI_CHUNK * 8 * 60) / THREADS; k++) {
            int idx = tid + k * THREADS;
            int ci  = idx / 480;
            int rem = idx % 480;
            int r   = rem / 60;
            int cc  = rem % 60;
            int h   = h_base - 1 + r;
            int w   = cc - 1;
            float v = 0.0f;
            if (h >= 0 && h < HW_H && w >= 0 && w < HW_W && cc < 58)
                v = xb[(ci0 + ci) * HW + h * HW_W + w];
            s_in[idx] = v;
        }

        // ---- stage weights: 8 ci x 9 taps x 64 oc (coalesced) ----
        #pragma unroll
        for (int k = 0; k < (CI_CHUNK * KTAPS * OC_TILE) / THREADS; k++) {
            int idx   = tid + k * THREADS;
            int citap = idx / OC_TILE;
            int oc    = idx % OC_TILE;
            s_w[idx]  = g_wt[(ci0 * KTAPS + citap) * COUT + blockIdx.x * OC_TILE + oc];
        }

        __syncthreads();

        // ---- compute ----
        for (int ci = 0; ci < CI_CHUNK; ci++) {
            const float* wrow = s_w  + ci * (KTAPS * OC_TILE) + warp * 8;
            const float* brow = s_in + ci * 480;
            #pragma unroll
            for (int tap = 0; tap < KTAPS; tap++) {
                const int dy = tap / 3, dx = tap % 3;
                const int toff = (dy - 1) * 60 + (dx - 1);
                float4 a0 = *reinterpret_cast<const float4*>(wrow + tap * OC_TILE);
                float4 a1 = *reinterpret_cast<const float4*>(wrow + tap * OC_TILE + 4);
                #pragma unroll
                for (int i = 0; i < 8; i++) {
                    float b = brow[boff[i] + toff];
                    acc[i][0] += b * a0.x;
                    acc[i][1] += b * a0.y;
                    acc[i][2] += b * a0.z;
                    acc[i][3] += b * a0.w;
                    acc[i][4] += b * a1.x;
                    acc[i][5] += b * a1.y;
                    acc[i][6] += b * a1.z;
                    acc[i][7] += b * a1.w;
                }
            }
        }
    }

    // ---- epilogue: bias + store (coalesced: lanes are consecutive p) ----
    float bv[8];
    #pragma unroll
    for (int j = 0; j < 8; j++) bv[j] = bias[oc0 + j];

    float* outn = out + ((size_t)n * COUT + oc0) * HW;
    #pragma unroll
    for (int i = 0; i < 8; i++) {
        if (pidx[i] < HW) {
            #pragma unroll
            for (int j = 0; j < 8; j++)
                outn[(size_t)j * HW + pidx[i]] = acc[i][j] + bv[j];
        }
    }
}

// ---------------------------------------------------------------------------
// Launch
// ---------------------------------------------------------------------------
extern "C" void kernel_launch(void* const* d_in, const int* in_sizes, int n_in,
                              void* d_out, int out_size) {
    const float* x      = (const float*)d_in[0];   // [32,256,56,56]
    const float* weight = (const float*)d_in[1];   // [256,256,3,3]
    const float* bias   = (const float*)d_in[2];   // [256]
    float* out = (float*)d_out;

    // 1) binarize activations
    {
        int n2 = BATCH * CIN * HW / 2;
        int blocks = (n2 + 255) / 256;
        binarize_kernel<<<blocks, 256>>>(x, n2);
    }
    // 2) transpose weights
    {
        int n = COUT * CIN * KTAPS;
        int blocks = (n + 255) / 256;
        wtrans_kernel<<<blocks, 256>>>(weight);
    }
    // 3) conv
    {
        dim3 grid(COUT / OC_TILE,                    // 4 oc tiles
                  (HW + POS_TILE - 1) / POS_TILE,    // 13 position tiles
                  BATCH);                            // 32 images
        conv3x3_kernel<<<grid, THREADS>>>(bias, out);
    }
    (void)in_sizes; (void)n_in; (void)out_size;
}

// round 4
// speedup vs baseline: 5.9213x; 5.9213x over previous
#include <cuda_runtime.h>
#include <cuda_fp16.h>
#include <math.h>
#include <stdint.h>

// ---------------------------------------------------------------------------
// Problem constants
// ---------------------------------------------------------------------------
#define BATCH 32
#define CIN   256
#define COUT  256
#define HW_H  56
#define HW_W  56
#define HW    3136
#define KTAPS 9

#define M_TILE   128
#define KC       64                       // ci per K chunk (4 k16 steps)
#define NCHUNKS  (KTAPS * (CIN / KC))     // 36
#define THREADS  512
#define STAGES   3
#define A_BYTES  (M_TILE * KC * 2)        // 16384
#define B_BYTES  (COUT * KC * 2)          // 32768
#define STAGE_BYTES (A_BYTES + B_BYTES)   // 49152
#define SMEM_DYN (STAGES * STAGE_BYTES)   // 147456

// ---------------------------------------------------------------------------
// Global scratch (__device__ arrays = allowed scratch)
// ---------------------------------------------------------------------------
__device__ __align__(16) __half g_a[(size_t)BATCH * HW * CIN];   // NHWC fp16
__device__ __align__(16) __half g_w[KTAPS * COUT * CIN];         // [tap][oc][ci]

// ---------------------------------------------------------------------------
// Small PTX helpers (sm_80-class features only: compute_103-safe)
// ---------------------------------------------------------------------------
__device__ __forceinline__ uint32_t smem_u32(const void* p) {
    uint32_t a;
    asm("{ .reg .u64 t; cvta.to.shared.u64 t, %1; cvt.u32.u64 %0, t; }"
        : "=r"(a) : "l"(p));
    return a;
}
#define CP_ASYNC16(dst, src, sz) \
    asm volatile("cp.async.ca.shared.global [%0], [%1], 16, %2;" \
        :: "r"(dst), "l"(src), "r"(sz) : "memory")
#define CP_COMMIT() asm volatile("cp.async.commit_group;" ::: "memory")
#define CP_WAIT1()  asm volatile("cp.async.wait_group 1;" ::: "memory")

#define LDSM_X4(r, addr) \
    asm volatile("ldmatrix.sync.aligned.m8n8.x4.shared.b16 {%0,%1,%2,%3}, [%4];" \
        : "=r"((r)[0]), "=r"((r)[1]), "=r"((r)[2]), "=r"((r)[3]) : "r"(addr))

#define MMA16816(d, a, b0v, b1v) \
    asm volatile("mma.sync.aligned.m16n8k16.row.col.f32.f16.f16.f32 " \
        "{%0,%1,%2,%3}, {%4,%5,%6,%7}, {%8,%9}, {%0,%1,%2,%3};" \
        : "+f"((d)[0]), "+f"((d)[1]), "+f"((d)[2]), "+f"((d)[3]) \
        : "r"((a)[0]), "r"((a)[1]), "r"((a)[2]), "r"((a)[3]), \
          "r"(b0v), "r"(b1v))

// ---------------------------------------------------------------------------
// Kernel 1: binarize (pair mean of |x| with sign of x) + fp16 + NCHW->NHWC
// Tile: 32 ci x 64 positions per block.
// ---------------------------------------------------------------------------
__global__ void binsplit_kernel(const float* __restrict__ x) {
    __shared__ __half s[64][56];                 // 112B row stride (16B mult)
    const int n = blockIdx.z, ci0 = blockIdx.y * 32, pos0 = blockIdx.x * 64;
    const int tid = threadIdx.x;

    #pragma unroll
    for (int i = 0; i < 4; i++) {
        int unit = tid + i * 256;
        int cl = unit >> 5;          // ci lane 0..31
        int pp = unit & 31;          // pair idx 0..31
        float2 v = *reinterpret_cast<const float2*>(
            x + ((size_t)(n * CIN + ci0 + cl) * HW + pos0 + pp * 2));
        float m = 0.5f * (fabsf(v.x) + fabsf(v.y));
        float a = (v.x == 0.0f) ? 0.0f : copysignf(m, v.x);
        float b = (v.y == 0.0f) ? 0.0f : copysignf(m, v.y);
        s[pp * 2    ][cl] = __float2half(a);
        s[pp * 2 + 1][cl] = __float2half(b);
    }
    __syncthreads();

    int pl = tid >> 2;       // position 0..63
    int c8 = tid & 3;        // 8-ci group
    size_t dst = ((size_t)n * HW + pos0 + pl) * CIN + ci0 + c8 * 8;
    *reinterpret_cast<uint4*>(g_a + dst) =
        *reinterpret_cast<const uint4*>(&s[pl][c8 * 8]);
}

// ---------------------------------------------------------------------------
// Kernel 2: weights OIHW -> fp16 [tap][oc][ci]
// ---------------------------------------------------------------------------
__global__ void wsplit_kernel(const float* __restrict__ w) {
    int idx = blockIdx.x * blockDim.x + threadIdx.x;
    if (idx >= COUT * CIN * KTAPS) return;
    int oc  = idx / (CIN * KTAPS);
    int rem = idx % (CIN * KTAPS);
    int ci  = rem / KTAPS;
    int tap = rem % KTAPS;
    g_w[((size_t)tap * COUT + oc) * CIN + ci] = __float2half(w[idx]);
}

// ---------------------------------------------------------------------------
// Kernel 3: implicit-GEMM 3x3 conv via mma.sync fp16 (single pass).
// CTA: 128 M-rows x 256 N (all oc). 16 warps in 4x4 grid, warp tile 32Mx64N.
// 3-stage cp.async pipeline over 36 (tap, ci-chunk) K chunks.
// ---------------------------------------------------------------------------
__global__ __launch_bounds__(THREADS, 1)
void conv_hmma_kernel(const float* __restrict__ bias, float* __restrict__ out) {
    extern __shared__ __align__(1024) char smem[];
    __shared__ float s_bias[COUT];

    const int tid  = threadIdx.x;
    const int warp = tid >> 5;
    const int lane = tid & 31;
    const int m0   = blockIdx.x * M_TILE;
    const uint32_t sb = smem_u32(smem);

    if (tid < COUT) s_bias[tid] = bias[tid];

    // ---- producer geometry (chunk-invariant) ----
    int a_u[2], a_h[2], a_w[2];
    uint32_t a_dst[2];
    const __half* a_base[2];
    #pragma unroll
    for (int i = 0; i < 2; i++) {
        int unit = tid + i * THREADS;
        int r = unit >> 3;  a_u[i] = unit & 7;
        int m = m0 + r;
        int img = m / HW, pos = m % HW;
        a_h[i] = pos / HW_W; a_w[i] = pos % HW_W;
        a_base[i] = g_a + (size_t)img * HW * CIN + a_u[i] * 8;
        a_dst[i] = (uint32_t)(r * 128 + ((a_u[i] ^ (r & 7)) * 16));
    }
    uint32_t b_dst[4]; int b_off[4];
    #pragma unroll
    for (int i = 0; i < 4; i++) {
        int unit = tid + i * THREADS;
        int r = unit >> 3, u = unit & 7;
        b_dst[i] = (uint32_t)(r * 128 + ((u ^ (r & 7)) * 16));
        b_off[i] = r * CIN + u * 8;
    }

    auto load_chunk = [&](int c, int stage) {
        int tap = c >> 2, ci0 = (c & 3) * KC;
        int dy = tap / 3 - 1, dx = tap % 3 - 1;
        uint32_t ab = sb + stage * STAGE_BYTES;
        #pragma unroll
        for (int i = 0; i < 2; i++) {
            int h2 = a_h[i] + dy, w2 = a_w[i] + dx;
            bool valid = ((unsigned)h2 < HW_H) && ((unsigned)w2 < HW_W);
            int hh = valid ? h2 : 0, ww = valid ? w2 : 0;
            const __half* src = a_base[i] + ((size_t)hh * HW_W + ww) * CIN + ci0;
            int sz = valid ? 16 : 0;
            CP_ASYNC16(ab + a_dst[i], src, sz);
        }
        uint32_t bb = ab + A_BYTES;
        const __half* wsrc = g_w + (size_t)tap * COUT * CIN + ci0;
        #pragma unroll
        for (int i = 0; i < 4; i++)
            CP_ASYNC16(bb + b_dst[i], wsrc + b_off[i], 16);
    };

    // ---- consumer geometry ----
    const int wm = warp >> 2, wn = warp & 3;
    const int arow = wm * 32 + (lane & 15);
    const int ach  = lane >> 4;                       // 0/1 k-16B-chunk
    const int brow = wn * 64 + (lane & 7) + ((lane >> 4) << 3);
    const int bch  = (lane >> 3) & 1;

    float acc[2][8][4];
    #pragma unroll
    for (int i = 0; i < 2; i++)
        #pragma unroll
        for (int j = 0; j < 8; j++)
            #pragma unroll
            for (int k = 0; k < 4; k++) acc[i][j][k] = 0.0f;

    auto compute_stage = [&](int stage) {
        uint32_t Ab = sb + stage * STAGE_BYTES;
        uint32_t Bb = Ab + A_BYTES;
        #pragma unroll
        for (int ks = 0; ks < 4; ks++) {
            uint32_t a[2][4], b[4][4];
            #pragma unroll
            for (int mt = 0; mt < 2; mt++) {
                uint32_t addr = Ab + (uint32_t)((arow + mt * 16) * 128 +
                                (((ks * 2 + ach) ^ (arow & 7)) * 16));
                LDSM_X4(a[mt], addr);
            }
            #pragma unroll
            for (int ng = 0; ng < 4; ng++) {
                uint32_t addr = Bb + (uint32_t)((brow + ng * 16) * 128 +
                                (((ks * 2 + bch) ^ (brow & 7)) * 16));
                LDSM_X4(b[ng], addr);
            }
            #pragma unroll
            for (int mt = 0; mt < 2; mt++)
                #pragma unroll
                for (int ng = 0; ng < 4; ng++) {
                    MMA16816(acc[mt][2 * ng],     a[mt], b[ng][0], b[ng][1]);
                    MMA16816(acc[mt][2 * ng + 1], a[mt], b[ng][2], b[ng][3]);
                }
        }
    };

    // ---- 3-stage pipeline ----
    load_chunk(0, 0); CP_COMMIT();
    load_chunk(1, 1); CP_COMMIT();

    int st = 0, ld = 2;
    #pragma unroll 1
    for (int c = 0; c < NCHUNKS; c++) {
        CP_WAIT1();
        __syncthreads();
        if (c + 2 < NCHUNKS) load_chunk(c + 2, ld);
        CP_COMMIT();
        ld = (ld == 2) ? 0 : ld + 1;
        compute_stage(st);
        st = (st == 2) ? 0 : st + 1;
    }

    // ---- epilogue: smem transpose -> coalesced NCHW stores + bias ----
    __syncthreads();
    float* epi = reinterpret_cast<float*>(smem) + warp * (64 * 33);
    #pragma unroll
    for (int mt = 0; mt < 2; mt++)
        #pragma unroll
        for (int nt = 0; nt < 8; nt++) {
            int nloc = nt * 8 + (lane & 3) * 2;
            int mloc = mt * 16 + (lane >> 2);
            epi[ nloc      * 33 + mloc    ] = acc[mt][nt][0];
            epi[(nloc + 1) * 33 + mloc    ] = acc[mt][nt][1];
            epi[ nloc      * 33 + mloc + 8] = acc[mt][nt][2];
            epi[(nloc + 1) * 33 + mloc + 8] = acc[mt][nt][3];
        }
    __syncwarp();

    int m = m0 + wm * 32 + lane;
    int img = m / HW, pos = m % HW;
    float* ob = out + (size_t)img * COUT * HW + pos;
    #pragma unroll 4
    for (int nloc = 0; nloc < 64; nloc++) {
        int oc = wn * 64 + nloc;
        ob[(size_t)oc * HW] = epi[nloc * 33 + lane] + s_bias[oc];
    }
}

// ---------------------------------------------------------------------------
// Launch
// ---------------------------------------------------------------------------
extern "C" void kernel_launch(void* const* d_in, const int* in_sizes, int n_in,
                              void* d_out, int out_size) {
    const float* x      = (const float*)d_in[0];   // [32,256,56,56]
    const float* weight = (const float*)d_in[1];   // [256,256,3,3]
    const float* bias   = (const float*)d_in[2];   // [256]
    float* out = (float*)d_out;

    // 1) binarize + fp16 + NHWC transpose
    {
        dim3 grid(HW / 64, CIN / 32, BATCH);       // (49, 8, 32)
        binsplit_kernel<<<grid, 256>>>(x);
    }
    // 2) weight convert/transpose
    {
        int n = COUT * CIN * KTAPS;
        wsplit_kernel<<<(n + 255) / 256, 256>>>(weight);
    }
    // 3) HMMA implicit-GEMM conv
    {
        cudaFuncSetAttribute(conv_hmma_kernel,
                             cudaFuncAttributeMaxDynamicSharedMemorySize,
                             SMEM_DYN);
        int m_tiles = (BATCH * HW) / M_TILE;       // 784
        conv_hmma_kernel<<<m_tiles, THREADS, SMEM_DYN>>>(bias, out);
    }
    (void)in_sizes; (void)n_in; (void)out_size;
}